// round 2
// baseline (speedup 1.0000x reference)
#include <cuda_runtime.h>
#include <cuda_bf16.h>

#define DT_F      0.1f
#define PI_F      3.14159265358979323846f
#define TWO_PI_F  6.28318530717958647692f

// One thread processes 4 consecutive rows.
// x: [B,5] f32 row-major  -> 4 rows = 20 floats = 5 aligned float4 (base 80B-aligned)
// a: [B,2], noise: [B,2]  -> 4 rows = 8 floats  = 2 aligned float4
// out: [B*5 next_x floats][B reached floats]
__global__ void __launch_bounds__(256, 8) Model_72026601554419_kernel(
    const float4* __restrict__ x4,
    const float4* __restrict__ a4,
    const float4* __restrict__ n4,
    const float*  __restrict__ pro_gains,
    const float*  __restrict__ pro_noise_ln_vars,
    const float*  __restrict__ goal_radius,
    float4* __restrict__ outx4,
    float4* __restrict__ outf4,
    int nquads)
{
    int t = blockIdx.x * blockDim.x + threadIdx.x;
    if (t >= nquads) return;

    // Uniform scalars (L1/const-cache broadcast)
    const float g0  = __ldg(pro_gains);
    const float g1  = __ldg(pro_gains + 1);
    const float s0  = __expf(0.5f * __ldg(pro_noise_ln_vars));      // sqrt(exp(v))
    const float s1  = __expf(0.5f * __ldg(pro_noise_ln_vars + 1));
    const float grv = __ldg(goal_radius);

    // Front-batched vector loads: 9 independent LDG.128 -> high MLP
    float xv[20];
    float av[8];
    float nv[8];
#pragma unroll
    for (int i = 0; i < 5; i++) reinterpret_cast<float4*>(xv)[i] = x4[(size_t)t * 5 + i];
#pragma unroll
    for (int i = 0; i < 2; i++) reinterpret_cast<float4*>(av)[i] = a4[(size_t)t * 2 + i];
#pragma unroll
    for (int i = 0; i < 2; i++) reinterpret_cast<float4*>(nv)[i] = n4[(size_t)t * 2 + i];

    float ov[20];
    float fv[4];

#pragma unroll
    for (int j = 0; j < 4; j++) {
        float px  = xv[5 * j + 0];
        float py  = xv[5 * j + 1];
        float ang = xv[5 * j + 2];

        float vel     = fmaf(g0, av[2 * j + 0], s0 * nv[2 * j + 0]);
        float ang_vel = fmaf(g1, av[2 * j + 1], s1 * nv[2 * j + 1]);

        // range_angle(ang + ang_vel*DT): jnp.mod semantics (result in [0, 2pi) before -pi)
        float an = fmaf(ang_vel, DT_F, ang) + PI_F;
        an = fmodf(an, TWO_PI_F);
        if (an < 0.0f) an += TWO_PI_F;
        an -= PI_F;

        float s, c;
        __sincosf(an, &s, &c);

        px = fminf(fmaxf(fmaf(vel * c, DT_F, px), -1.0f), 1.0f);
        py = fminf(fmaxf(fmaf(vel * s, DT_F, py), -1.0f), 1.0f);

        ov[5 * j + 0] = px;
        ov[5 * j + 1] = py;
        ov[5 * j + 2] = an;
        ov[5 * j + 3] = vel;
        ov[5 * j + 4] = ang_vel;

        fv[j] = (sqrtf(fmaf(px, px, py * py)) <= grv) ? 1.0f : 0.0f;
    }

    // Coalesced vector stores: 5x STG.128 for next_x rows, 1x STG.128 for flags
#pragma unroll
    for (int i = 0; i < 5; i++) outx4[(size_t)t * 5 + i] = reinterpret_cast<float4*>(ov)[i];
    outf4[t] = reinterpret_cast<float4*>(fv)[0];
}

extern "C" void kernel_launch(void* const* d_in, const int* in_sizes, int n_in,
                              void* d_out, int out_size)
{
    const float* x     = (const float*)d_in[0];  // [B,5]
    const float* a     = (const float*)d_in[1];  // [B,2]
    const float* noise = (const float*)d_in[2];  // [B,2]
    const float* pg    = (const float*)d_in[3];  // [2]
    const float* pv    = (const float*)d_in[4];  // [2]
    const float* gr    = (const float*)d_in[5];  // [1]

    const int B = in_sizes[0] / 5;
    float* out      = (float*)d_out;             // [B*5] next_x
    float* out_flag = out + (size_t)B * 5;       // [B] reached_target as 0/1 float

    const int nquads  = B / 4;                   // B = 8388608, divisible by 4
    const int threads = 256;
    const int blocks  = (nquads + threads - 1) / threads;

    Model_72026601554419_kernel<<<blocks, threads>>>(
        (const float4*)x, (const float4*)a, (const float4*)noise,
        pg, pv, gr,
        (float4*)out, (float4*)out_flag, nquads);
}

// round 5
// speedup vs baseline: 1.2354x; 1.2354x over previous
#include <cuda_runtime.h>
#include <cuda_bf16.h>

#define DT_F      0.1f
#define PI_F      3.14159265358979323846f
#define TWO_PI_F  6.28318530717958647692f

#define NTHREADS        256
#define ROWS_PER_THREAD 4
#define ROWS_PER_BLOCK  (NTHREADS * ROWS_PER_THREAD)   // 1024 rows
#define XFLOATS         (ROWS_PER_BLOCK * 5)           // 5120 floats of x per block
#define XF4             (XFLOATS / 4)                  // 1280 float4 (5 per thread)
// padded smem: one pad word per 5-float row -> per-thread region stride = 21 words
// (21 odd => conflict-free scalar LDS/STS across lanes)
#define SMEM_WORDS      (XFLOATS + XFLOATS / 20)       // 5376 words = 21504 B

__global__ void __launch_bounds__(NTHREADS, 6) Model_72026601554419_kernel(
    const float4* __restrict__ x4,
    const float4* __restrict__ a4,
    const float4* __restrict__ n4,
    const float*  __restrict__ pro_gains,
    const float*  __restrict__ pro_noise_ln_vars,
    const float*  __restrict__ goal_radius,
    float4* __restrict__ outx4,
    float4* __restrict__ outf4)
{
    __shared__ float s[SMEM_WORDS];

    const int    tid    = threadIdx.x;
    const int    t      = blockIdx.x * NTHREADS + tid;   // quad index (4 rows)
    const size_t xbase4 = (size_t)blockIdx.x * XF4;      // block's x base (float4 units)

    // Independent early loads: a, noise (direct; 32B lane stride, minor inflation)
    const float4 aA = a4[(size_t)t * 2 + 0];
    const float4 aB = a4[(size_t)t * 2 + 1];
    const float4 nA = n4[(size_t)t * 2 + 0];
    const float4 nB = n4[(size_t)t * 2 + 1];

    const float g0  = __ldg(pro_gains);
    const float g1  = __ldg(pro_gains + 1);
    const float s0  = __expf(0.5f * __ldg(pro_noise_ln_vars));      // sqrt(exp(v))
    const float s1  = __expf(0.5f * __ldg(pro_noise_ln_vars + 1));
    const float grv = __ldg(goal_radius);

    // Phase A: fully-coalesced x load (unit lane stride), scatter to padded smem.
    // Row boundaries (every 20 floats) align to float4 groups, so f/20 is
    // constant within each group.
#pragma unroll
    for (int i = 0; i < 5; i++) {
        const int    gq  = tid + NTHREADS * i;           // local float4 idx 0..1279
        const float4 val = x4[xbase4 + gq];
        const int    f   = 4 * gq;
        const int    idx = f + f / 20;
        s[idx + 0] = val.x; s[idx + 1] = val.y;
        s[idx + 2] = val.z; s[idx + 3] = val.w;
    }
    __syncthreads();

    // Phase B: thread t owns rows 4t..4t+3 in s[21t .. 21t+20). Own-region
    // read + in-place writeback => no cross-thread hazard, no extra sync.
    const float av[8] = {aA.x, aA.y, aA.z, aA.w, aB.x, aB.y, aB.z, aB.w};
    const float nv[8] = {nA.x, nA.y, nA.z, nA.w, nB.x, nB.y, nB.z, nB.w};
    float fv[4];
    const int base = 21 * tid;

#pragma unroll
    for (int j = 0; j < 4; j++) {
        float px  = s[base + 5 * j + 0];
        float py  = s[base + 5 * j + 1];
        float ang = s[base + 5 * j + 2];

        // Match reference op order/rounding (no FMA contraction)
        float vel     = __fadd_rn(__fmul_rn(g0, av[2 * j + 0]), __fmul_rn(s0, nv[2 * j + 0]));
        float ang_vel = __fadd_rn(__fmul_rn(g1, av[2 * j + 1]), __fmul_rn(s1, nv[2 * j + 1]));

        // range_angle: mod(ang + ang_vel*DT + pi, 2pi) - pi  (jnp.mod semantics)
        float an = __fadd_rn(__fadd_rn(ang, __fmul_rn(ang_vel, DT_F)), PI_F);
        an = fmodf(an, TWO_PI_F);
        if (an < 0.0f) an += TWO_PI_F;
        an -= PI_F;

        float sn, cs;
        sincosf(an, &sn, &cs);   // precise variant: buys rel_err margin, time is free

        px = fminf(fmaxf(__fadd_rn(px, __fmul_rn(__fmul_rn(vel, cs), DT_F)), -1.0f), 1.0f);
        py = fminf(fmaxf(__fadd_rn(py, __fmul_rn(__fmul_rn(vel, sn), DT_F)), -1.0f), 1.0f);

        s[base + 5 * j + 0] = px;
        s[base + 5 * j + 1] = py;
        s[base + 5 * j + 2] = an;
        s[base + 5 * j + 3] = vel;
        s[base + 5 * j + 4] = ang_vel;

        const float d2 = __fadd_rn(__fmul_rn(px, px), __fmul_rn(py, py));
        fv[j] = (sqrtf(d2) <= grv) ? 1.0f : 0.0f;
    }

    // Flags: contiguous 16B per thread -> already coalesced
    outf4[t] = make_float4(fv[0], fv[1], fv[2], fv[3]);
    __syncthreads();

    // Phase C: gather from padded smem, fully-coalesced STG.128
#pragma unroll
    for (int i = 0; i < 5; i++) {
        const int gq  = tid + NTHREADS * i;
        const int f   = 4 * gq;
        const int idx = f + f / 20;
        outx4[xbase4 + gq] = make_float4(s[idx + 0], s[idx + 1], s[idx + 2], s[idx + 3]);
    }
}

extern "C" void kernel_launch(void* const* d_in, const int* in_sizes, int n_in,
                              void* d_out, int out_size)
{
    const float* x     = (const float*)d_in[0];  // [B,5]
    const float* a     = (const float*)d_in[1];  // [B,2]
    const float* noise = (const float*)d_in[2];  // [B,2]
    const float* pg    = (const float*)d_in[3];  // [2]
    const float* pv    = (const float*)d_in[4];  // [2]
    const float* gr    = (const float*)d_in[5];  // [1]

    const int B = in_sizes[0] / 5;               // 8388608 (divisible by 1024)
    float* out      = (float*)d_out;             // [B*5] next_x
    float* out_flag = out + (size_t)B * 5;       // [B] reached_target as 0/1 float

    const int blocks = B / ROWS_PER_BLOCK;       // 8192

    Model_72026601554419_kernel<<<blocks, NTHREADS>>>(
        (const float4*)x, (const float4*)a, (const float4*)noise,
        pg, pv, gr,
        (float4*)out, (float4*)out_flag);
}

// round 6
// speedup vs baseline: 1.2451x; 1.0079x over previous
#include <cuda_runtime.h>
#include <cuda_bf16.h>
#include <cstdint>

#define DT_F      0.1f
#define PI_F      3.14159265358979323846f
#define TWO_PI_F  6.28318530717958647692f

#define NTHREADS       256
#define ROWS_PER_BLOCK 512                       // 2 rows per thread: t and t+256
#define X_FLOATS       (ROWS_PER_BLOCK * 5)      // 2560 floats = 10240 B
#define AN_FLOATS      (ROWS_PER_BLOCK * 2)      // 1024 floats = 4096 B
#define TX_BYTES       (X_FLOATS * 4 + 2 * AN_FLOATS * 4)   // 18432

__device__ __forceinline__ uint32_t smem_u32(const void* p) {
    uint32_t a;
    asm("{ .reg .u64 t; cvta.to.shared.u64 t, %1; cvt.u32.u64 %0, t; }" : "=r"(a) : "l"(p));
    return a;
}

__global__ void __launch_bounds__(NTHREADS, 8) Model_72026601554419_kernel(
    const float* __restrict__ x_g,
    const float* __restrict__ a_g,
    const float* __restrict__ n_g,
    const float* __restrict__ pro_gains,
    const float* __restrict__ pro_noise_ln_vars,
    const float* __restrict__ goal_radius,
    float*       __restrict__ outx_g,
    float*       __restrict__ outf_g)
{
    __shared__ __align__(128) float sx[X_FLOATS];   // x slab, reused in-place for output
    __shared__ __align__(16)  float sa[AN_FLOATS];
    __shared__ __align__(16)  float sn[AN_FLOATS];
    __shared__ __align__(8)   uint64_t mbar;

    const int tid = threadIdx.x;
    const size_t blk = blockIdx.x;

    const float* xg = x_g + blk * X_FLOATS;
    const float* ag = a_g + blk * AN_FLOATS;
    const float* ng = n_g + blk * AN_FLOATS;

    // Uniform scalars early (overlap with TMA)
    const float g0  = __ldg(pro_gains);
    const float g1  = __ldg(pro_gains + 1);
    const float s0  = __expf(0.5f * __ldg(pro_noise_ln_vars));      // sqrt(exp(v))
    const float s1  = __expf(0.5f * __ldg(pro_noise_ln_vars + 1));
    const float grv = __ldg(goal_radius);

    const uint32_t mb = smem_u32(&mbar);

    if (tid == 0) {
        asm volatile("mbarrier.init.shared::cta.b64 [%0], 1;" :: "r"(mb) : "memory");
    }
    __syncthreads();   // mbarrier visible to all before anyone polls

    if (tid == 0) {
        asm volatile("mbarrier.arrive.expect_tx.shared::cta.b64 _, [%0], %1;"
                     :: "r"(mb), "r"((uint32_t)TX_BYTES) : "memory");
        asm volatile("cp.async.bulk.shared::cluster.global.mbarrier::complete_tx::bytes "
                     "[%0], [%1], %2, [%3];"
                     :: "r"(smem_u32(sx)), "l"(xg), "r"((uint32_t)(X_FLOATS * 4)), "r"(mb) : "memory");
        asm volatile("cp.async.bulk.shared::cluster.global.mbarrier::complete_tx::bytes "
                     "[%0], [%1], %2, [%3];"
                     :: "r"(smem_u32(sa)), "l"(ag), "r"((uint32_t)(AN_FLOATS * 4)), "r"(mb) : "memory");
        asm volatile("cp.async.bulk.shared::cluster.global.mbarrier::complete_tx::bytes "
                     "[%0], [%1], %2, [%3];"
                     :: "r"(smem_u32(sn)), "l"(ng), "r"((uint32_t)(AN_FLOATS * 4)), "r"(mb) : "memory");
    }

    // Wait for all three bulk loads (acquire orders TMA data before our LDS)
    {
        asm volatile(
            "{\n\t.reg .pred P;\n\t"
            "W_%=:\n\t"
            "mbarrier.try_wait.parity.acquire.cta.shared::cta.b64 P, [%0], %1, 0x989680;\n\t"
            "@P bra D_%=;\n\t"
            "bra W_%=;\n\t"
            "D_%=:\n\t}"
            :: "r"(mb), "r"(0u) : "memory");
    }

    // Each thread owns rows tid and tid+256.
    // x row r at word 5r: stride 5 (odd) -> conflict-free scalar LDS/STS.
    // a/n row r at float2 idx r: unit stride -> conflict-free LDS.64.
    const float2* sa2 = reinterpret_cast<const float2*>(sa);
    const float2* sn2 = reinterpret_cast<const float2*>(sn);
    float flags[2];

#pragma unroll
    for (int half = 0; half < 2; half++) {
        const int r = tid + half * NTHREADS;

        const float2 ar = sa2[r];
        const float2 nr = sn2[r];

        float px  = sx[5 * r + 0];
        float py  = sx[5 * r + 1];
        float ang = sx[5 * r + 2];

        // Match reference op order/rounding (no FMA contraction)
        float vel     = __fadd_rn(__fmul_rn(g0, ar.x), __fmul_rn(s0, nr.x));
        float ang_vel = __fadd_rn(__fmul_rn(g1, ar.y), __fmul_rn(s1, nr.y));

        // range_angle: mod(ang + ang_vel*DT + pi, 2pi) - pi  (jnp.mod semantics)
        float an = __fadd_rn(__fadd_rn(ang, __fmul_rn(ang_vel, DT_F)), PI_F);
        an = fmodf(an, TWO_PI_F);
        if (an < 0.0f) an += TWO_PI_F;
        an -= PI_F;

        float sn_v, cs_v;
        sincosf(an, &sn_v, &cs_v);

        px = fminf(fmaxf(__fadd_rn(px, __fmul_rn(__fmul_rn(vel, cs_v), DT_F)), -1.0f), 1.0f);
        py = fminf(fmaxf(__fadd_rn(py, __fmul_rn(__fmul_rn(vel, sn_v), DT_F)), -1.0f), 1.0f);

        sx[5 * r + 0] = px;
        sx[5 * r + 1] = py;
        sx[5 * r + 2] = an;
        sx[5 * r + 3] = vel;
        sx[5 * r + 4] = ang_vel;

        const float d2 = __fadd_rn(__fmul_rn(px, px), __fmul_rn(py, py));
        flags[half] = (sqrtf(d2) <= grv) ? 1.0f : 0.0f;
    }

    // Flags: direct coalesced scalar stores (unit lane stride)
    outf_g[blk * ROWS_PER_BLOCK + tid]            = flags[0];
    outf_g[blk * ROWS_PER_BLOCK + tid + NTHREADS] = flags[1];

    __syncthreads();   // all rows written to sx

    if (tid == 0) {
        asm volatile("fence.proxy.async.shared::cta;" ::: "memory");
        asm volatile("cp.async.bulk.global.shared::cta.bulk_group [%0], [%1], %2;"
                     :: "l"(outx_g + blk * X_FLOATS), "r"(smem_u32(sx)),
                        "r"((uint32_t)(X_FLOATS * 4)) : "memory");
        asm volatile("cp.async.bulk.commit_group;" ::: "memory");
        asm volatile("cp.async.bulk.wait_group 0;" ::: "memory");
    }
}

extern "C" void kernel_launch(void* const* d_in, const int* in_sizes, int n_in,
                              void* d_out, int out_size)
{
    const float* x     = (const float*)d_in[0];  // [B,5]
    const float* a     = (const float*)d_in[1];  // [B,2]
    const float* noise = (const float*)d_in[2];  // [B,2]
    const float* pg    = (const float*)d_in[3];  // [2]
    const float* pv    = (const float*)d_in[4];  // [2]
    const float* gr    = (const float*)d_in[5];  // [1]

    const int B = in_sizes[0] / 5;               // 8388608 (divisible by 512)
    float* out      = (float*)d_out;             // [B*5] next_x
    float* out_flag = out + (size_t)B * 5;       // [B] reached_target as 0/1 float

    const int blocks = B / ROWS_PER_BLOCK;       // 16384

    Model_72026601554419_kernel<<<blocks, NTHREADS>>>(
        x, a, noise, pg, pv, gr, out, out_flag);
}